// round 12
// baseline (speedup 1.0000x reference)
#include <cuda_runtime.h>
#include <cuda_fp16.h>
#include <math.h>
#include <stdint.h>

#define SSEQ 2048
#define DMODEL 1024
#define NHEADS 16
#define DKH 64
#define DFF 4096
#define ROWS 4096
#define ZTOT 32
#define SD ((long long)SSEQ*DMODEL)
typedef __half hf;

// ---------------- scratch ----------------
__device__ __align__(256) float g_t0[ROWS*DMODEL];
__device__ __align__(256) float g_x1[ROWS*DMODEL];
__device__ __align__(256) float g_gate[ZTOT*SSEQ];
__device__ __align__(256) unsigned char g_mflag[256];
__device__ __align__(256) hf g_xh[ROWS*DMODEL];
__device__ __align__(256) hf g_qh[ROWS*DMODEL];
__device__ __align__(256) hf g_kh[ROWS*DMODEL];
__device__ __align__(256) hf g_vh[ROWS*DMODEL];
__device__ __align__(256) hf g_ch[ROWS*DMODEL];
__device__ __align__(256) hf g_yh[ROWS*DMODEL];
__device__ __align__(256) hf g_fh[ROWS*DFF];
__device__ __align__(256) hf g_wqh[DMODEL*DMODEL];
__device__ __align__(256) hf g_wkh[DMODEL*DMODEL];
__device__ __align__(256) hf g_wvh[DMODEL*DMODEL];
__device__ __align__(256) hf g_woh[DMODEL*DMODEL];
__device__ __align__(256) hf g_w1h[DMODEL*DFF];
__device__ __align__(256) hf g_w2h[DMODEL*DFF];

// ---------------- helpers ----------------
__device__ __forceinline__ uint32_t su32(const void* p){uint32_t a;
    asm("{.reg .u64 t; cvta.to.shared.u64 t,%1; cvt.u32.u64 %0,t;}":"=r"(a):"l"(p));return a;}
__device__ __forceinline__ void cpa(uint32_t d,const void*s){
    asm volatile("cp.async.cg.shared.global [%0],[%1],16;"::"r"(d),"l"(s));}
#define CPCOMMIT() asm volatile("cp.async.commit_group;":::"memory")
#define LDM4(f,a) asm volatile("ldmatrix.sync.aligned.m8n8.x4.shared.b16 {%0,%1,%2,%3},[%4];" \
    :"=r"((f)[0]),"=r"((f)[1]),"=r"((f)[2]),"=r"((f)[3]):"r"(a))
#define LDM4B(b0,b1,b2,b3,a) asm volatile("ldmatrix.sync.aligned.m8n8.x4.shared.b16 {%0,%1,%2,%3},[%4];" \
    :"=r"(b0),"=r"(b1),"=r"(b2),"=r"(b3):"r"(a))
#define LDM4T(f,a) asm volatile("ldmatrix.sync.aligned.m8n8.x4.trans.shared.b16 {%0,%1,%2,%3},[%4];" \
    :"=r"((f)[0]),"=r"((f)[1]),"=r"((f)[2]),"=r"((f)[3]):"r"(a))
#define MMA(c,A,B) asm volatile( \
    "mma.sync.aligned.m16n8k16.row.col.f32.f16.f16.f32 {%0,%1,%2,%3},{%4,%5,%6,%7},{%8,%9},{%0,%1,%2,%3};" \
    :"+f"((c)[0]),"+f"((c)[1]),"+f"((c)[2]),"+f"((c)[3]) \
    :"r"((A)[0]),"r"((A)[1]),"r"((A)[2]),"r"((A)[3]),"r"((B)[0]),"r"((B)[1]))
#define MMAB(c,A,b0,b1) asm volatile( \
    "mma.sync.aligned.m16n8k16.row.col.f32.f16.f16.f32 {%0,%1,%2,%3},{%4,%5,%6,%7},{%8,%9},{%0,%1,%2,%3};" \
    :"+f"((c)[0]),"+f"((c)[1]),"+f"((c)[2]),"+f"((c)[3]) \
    :"r"((A)[0]),"r"((A)[1]),"r"((A)[2]),"r"((A)[3]),"r"(b0),"r"(b1))

__device__ __forceinline__ uint32_t pack2h(float a, float b){
    __half2 hp=__floats2half2_rn(a,b);
    return *(uint32_t*)&hp;
}

// ---------------- fp16 HMMA GEMM core ----------------
// CTA tile 64x128, warp tile 32x32 (8 warps: 2 along M x 4 along N), BK=32,
// 3-stage cp.async ring, 3 CTAs/SM (acc 32 regs/thread).
__device__ __forceinline__ void hgemm_body(
    const hf* __restrict__ A_, const hf* __restrict__ B_,
    int K, int lda, int ldb, int ldc,
    float* __restrict__ Cf, hf* __restrict__ Ch,
    const float* __restrict__ bias, const float* __restrict__ bias2,
    int epi, int outm)
{
    constexpr int ABYTES = 64*80;      // 5120
    constexpr int STG    = ABYTES + 128*80;  // 15360
    extern __shared__ char smraw[];
    uint32_t su = su32(smraw);
    int tid = threadIdx.x, wid = tid>>5, lane = tid&31;
    int wm = wid%2, wn = wid/2;
    int m0 = blockIdx.y*64, n0 = blockIdx.x*128;

    const hf* pA = A_ + (long long)m0*lda;
    const hf* pB = B_ + (long long)n0*ldb;
    int nk = K>>5;

    int r = tid>>2, sg = tid&3;       // r: 0..63
    auto loadstage = [&](int ci, int st){
        uint32_t b = su + (uint32_t)st*STG;
        int k0 = ci<<5;
        cpa(b + r*80 + sg*16, pA + (long long)r*lda + k0 + sg*8);
        #pragma unroll
        for(int p=0;p<2;p++){
            int rr = r + p*64;
            cpa(b + ABYTES + rr*80 + sg*16, pB + (long long)rr*ldb + k0 + sg*8);
        }
        CPCOMMIT();
    };

    float acc[2][4][4];
    #pragma unroll
    for(int a=0;a<2;a++)
        #pragma unroll
        for(int b=0;b<4;b++)
            #pragma unroll
            for(int c=0;c<4;c++) acc[a][b][c]=0.f;

    int quad = lane>>3, lq = lane&7;
    uint32_t aoff = (uint32_t)((wm*32 + (quad&1)*8 + lq)*80 + (quad>>1)*16);
    uint32_t boff = (uint32_t)(ABYTES + (wn*32 + (quad>>1)*8 + lq)*80 + (quad&1)*16);

    loadstage(0,0);
    if(nk>1) loadstage(1,1);

    int st = 0;
    for(int i=0;i<nk;i++){
        if(i+1<nk) asm volatile("cp.async.wait_group 1;":::"memory");
        else       asm volatile("cp.async.wait_group 0;":::"memory");
        __syncthreads();
        if(i+2<nk){
            int st2 = st+2; if(st2>=3) st2-=3;
            loadstage(i+2, st2);
        }
        uint32_t sb = su + (uint32_t)st*STG;
        uint32_t pa = sb + aoff, pb = sb + boff;
        uint32_t Af[2][4], Bf[4][2];
        #pragma unroll
        for(int ks=0;ks<2;ks++){
            uint32_t kso = ks*32;
            #pragma unroll
            for(int mt=0;mt<2;mt++) LDM4(Af[mt], pa + mt*1280 + kso);
            #pragma unroll
            for(int np=0;np<2;np++)
                LDM4B(Bf[2*np][0],Bf[2*np][1],Bf[2*np+1][0],Bf[2*np+1][1], pb + np*1280 + kso);
            #pragma unroll
            for(int mt=0;mt<2;mt++)
                #pragma unroll
                for(int nt=0;nt<4;nt++) MMA(acc[mt][nt],Af[mt],Bf[nt]);
        }
        if(++st==3) st=0;
    }

    auto store2 = [&](int row,int col,float v0,float v1){
        if(bias){ v0+=bias[col]; v1+=bias[col+1]; }
        if(bias2){ v0+=bias2[col]; v1+=bias2[col+1]; }
        if(epi==1){
            v0 = 0.5f*v0*(1.0f+erff(v0*0.70710678118654752f));
            v1 = 0.5f*v1*(1.0f+erff(v1*0.70710678118654752f));
        }
        if(outm==0){
            *(float2*)&Cf[(long long)row*ldc+col] = make_float2(v0,v1);
        } else {
            *(uint32_t*)(Ch+(long long)row*ldc+col) = pack2h(v0,v1);
        }
    };
    #pragma unroll
    for(int mt=0;mt<2;mt++){
        #pragma unroll
        for(int nt=0;nt<4;nt++){
            int row0 = m0 + wm*32 + mt*16 + (lane>>2);
            int col  = n0 + wn*32 + nt*8 + ((lane&3)<<1);
            store2(row0,   col, acc[mt][nt][0], acc[mt][nt][1]);
            store2(row0+8, col, acc[mt][nt][2], acc[mt][nt][3]);
        }
    }
}

__global__ __launch_bounds__(256,3) void hgemm(
    const hf* __restrict__ A_, const hf* __restrict__ B_,
    int K, int lda, int ldb, int ldc,
    float* __restrict__ Cf, hf* __restrict__ Ch,
    const float* __restrict__ bias, const float* __restrict__ bias2,
    int epi, int outm)
{
    hgemm_body(A_,B_,K,lda,ldb,ldc,Cf,Ch,bias,bias2,epi,outm);
}

// fused Q/K/V projections: blockIdx.z selects weight/output/bias
__global__ __launch_bounds__(256,3) void hgemm3(
    const hf* __restrict__ A_,
    const hf* __restrict__ Bq, const hf* __restrict__ Bk, const hf* __restrict__ Bv,
    hf* __restrict__ Cq, hf* __restrict__ Ck, hf* __restrict__ Cv,
    const float* __restrict__ bq, const float* __restrict__ bk, const float* __restrict__ bv,
    const float* __restrict__ tw)
{
    int z = blockIdx.z;
    const hf* B = (z==0)?Bq:(z==1)?Bk:Bv;
    hf* C = (z==0)?Cq:(z==1)?Ck:Cv;
    const float* bias = (z==0)?bq:(z==1)?bk:bv;
    const float* bias2 = (z==0)?tw:nullptr;
    hgemm_body(A_,B,DMODEL,DMODEL,DMODEL,DMODEL,nullptr,C,bias,bias2,0,1);
}

// ---------------- flash attention (fp16, 3-stage K/V ring, mask flags) ----
#define PITCH 144
__global__ __launch_bounds__(256,1) void flashattn(
    const hf* __restrict__ qh_, const hf* __restrict__ kh_, const hf* __restrict__ vh_,
    const int* __restrict__ mask, const unsigned char* __restrict__ mflag,
    const float* __restrict__ gate,
    const float* __restrict__ temp, hf* __restrict__ ch)
{
    extern __shared__ char sm[];
    uint32_t su = su32(sm);
    const uint32_t ST=18432, STSZ=36864;
    int tid=threadIdx.x, wid=tid>>5, lane=tid&31;
    int quad=lane>>3, lq=lane&7;
    int z=blockIdx.y, zb=z>>4, zh=z&15;
    int q0=blockIdx.x*128;
    long long hoff=(long long)zb*SD + zh*64;
    const hf* pq = qh_ + hoff + (long long)q0*DMODEL;

    int cc=tid&7, rr0=tid>>3;
    #pragma unroll
    for(int p=0;p<4;p++){
        int r=rr0+p*32;
        cpa(su + r*PITCH + cc*16, pq + (long long)r*DMODEL + cc*8);
    }
    CPCOMMIT();

    auto ldstage=[&](int it,int st){
        uint32_t b=su+ST+(uint32_t)st*STSZ;
        long long kbase=hoff + (long long)(it*128)*DMODEL;
        #pragma unroll
        for(int p=0;p<4;p++){
            int r=rr0+p*32;
            long long go=kbase+(long long)r*DMODEL+cc*8;
            uint32_t so=r*PITCH+cc*16;
            cpa(b+so, kh_+go);
            cpa(b+18432+so, vh_+go);
        }
        CPCOMMIT();
    };
    ldstage(0,0); ldstage(1,1);
    asm volatile("cp.async.wait_group 2;":::"memory");
    __syncthreads();

    uint32_t qaddr = su + (uint32_t)((wid*16 + (quad&1)*8 + lq)*PITCH + (quad>>1)*16);
    uint32_t qf[4][4];
    #pragma unroll
    for(int ks=0;ks<4;ks++) LDM4(qf[ks], qaddr+ks*32);

    int r0l = wid*16 + (lane>>2);
    float g0 = gate[(long long)z*SSEQ + q0 + r0l];
    float g1 = gate[(long long)z*SSEQ + q0 + r0l + 8];
    float invT = 1.f/temp[0];
    float m0=-1e30f,m1=-1e30f,l0=0.f,l1=0.f;
    float oacc[8][4];
    #pragma unroll
    for(int d=0;d<8;d++){oacc[d][0]=0;oacc[d][1]=0;oacc[d][2]=0;oacc[d][3]=0;}

    int st = 0;
    for(int it=0; it<16; it++){
        if(it<15) asm volatile("cp.async.wait_group 1;":::"memory");
        else      asm volatile("cp.async.wait_group 0;":::"memory");
        __syncthreads();
        if(it+2<16){
            int st2 = st+2; if(st2>=3) st2-=3;
            ldstage(it+2, st2);
        }
        uint32_t sb = su+ST+(uint32_t)st*STSZ;

        float sacc[16][4];
        #pragma unroll
        for(int nt=0;nt<16;nt++){sacc[nt][0]=0;sacc[nt][1]=0;sacc[nt][2]=0;sacc[nt][3]=0;}
        uint32_t baddr = sb + (uint32_t)((lq + 8*(quad>>1))*PITCH + (quad&1)*16);
        #pragma unroll
        for(int ks=0;ks<4;ks++){
            uint32_t b[16][2];
            #pragma unroll
            for(int j=0;j<8;j++)
                LDM4B(b[2*j][0],b[2*j][1],b[2*j+1][0],b[2*j+1][1], baddr + j*(16*PITCH) + ks*32);
            #pragma unroll
            for(int nt=0;nt<16;nt++) MMA(sacc[nt], qf[ks], b[nt]);
        }

        float rm0=-1e30f, rm1=-1e30f;
        if(mflag[(q0>>7)*16 + it]){
            #pragma unroll
            for(int nt=0;nt<16;nt++){
                float s0=sacc[nt][0]*invT, s1=sacc[nt][1]*invT;
                float s2=sacc[nt][2]*invT, s3=sacc[nt][3]*invT;
                s0*=g0;s1*=g0;s2*=g1;s3*=g1;
                sacc[nt][0]=s0;sacc[nt][1]=s1;sacc[nt][2]=s2;sacc[nt][3]=s3;
                rm0=fmaxf(rm0,fmaxf(s0,s1)); rm1=fmaxf(rm1,fmaxf(s2,s3));
            }
        } else {
            long long mrow0 = (long long)(q0 + r0l)*SSEQ + it*128 + 2*(lane&3);
            long long mrow1 = mrow0 + 8LL*SSEQ;
            #pragma unroll
            for(int nt=0;nt<16;nt++){
                int2 mA = *(const int2*)&mask[mrow0 + nt*8];
                int2 mB = *(const int2*)&mask[mrow1 + nt*8];
                float s0=sacc[nt][0]*invT, s1=sacc[nt][1]*invT;
                float s2=sacc[nt][2]*invT, s3=sacc[nt][3]*invT;
                if(mA.x==0)s0=-1e9f; if(mA.y==0)s1=-1e9f;
                if(mB.x==0)s2=-1e9f; if(mB.y==0)s3=-1e9f;
                s0*=g0;s1*=g0;s2*=g1;s3*=g1;
                sacc[nt][0]=s0;sacc[nt][1]=s1;sacc[nt][2]=s2;sacc[nt][3]=s3;
                rm0=fmaxf(rm0,fmaxf(s0,s1)); rm1=fmaxf(rm1,fmaxf(s2,s3));
            }
        }
        rm0=fmaxf(rm0,__shfl_xor_sync(~0u,rm0,1)); rm0=fmaxf(rm0,__shfl_xor_sync(~0u,rm0,2));
        rm1=fmaxf(rm1,__shfl_xor_sync(~0u,rm1,1)); rm1=fmaxf(rm1,__shfl_xor_sync(~0u,rm1,2));
        float mn0=fmaxf(m0,rm0), mn1=fmaxf(m1,rm1);
        float sc0=__expf(m0-mn0), sc1=__expf(m1-mn1);
        m0=mn0; m1=mn1;

        float rs0=0.f, rs1=0.f;
        #pragma unroll
        for(int nt=0;nt<16;nt++){
            float p0=__expf(sacc[nt][0]-m0), p1=__expf(sacc[nt][1]-m0);
            float p2=__expf(sacc[nt][2]-m1), p3=__expf(sacc[nt][3]-m1);
            sacc[nt][0]=p0;sacc[nt][1]=p1;sacc[nt][2]=p2;sacc[nt][3]=p3;
            rs0+=p0+p1; rs1+=p2+p3;
        }
        rs0+=__shfl_xor_sync(~0u,rs0,1); rs0+=__shfl_xor_sync(~0u,rs0,2);
        rs1+=__shfl_xor_sync(~0u,rs1,1); rs1+=__shfl_xor_sync(~0u,rs1,2);
        l0 = l0*sc0 + rs0; l1 = l1*sc1 + rs1;
        #pragma unroll
        for(int d=0;d<8;d++){ oacc[d][0]*=sc0; oacc[d][1]*=sc0; oacc[d][2]*=sc1; oacc[d][3]*=sc1; }

        #pragma unroll
        for(int kv=0;kv<8;kv++){
            uint32_t pa[4];
            pa[0]=pack2h(sacc[2*kv][0],   sacc[2*kv][1]);
            pa[1]=pack2h(sacc[2*kv][2],   sacc[2*kv][3]);
            pa[2]=pack2h(sacc[2*kv+1][0], sacc[2*kv+1][1]);
            pa[3]=pack2h(sacc[2*kv+1][2], sacc[2*kv+1][3]);
            uint32_t vbase = sb + 18432 + (uint32_t)((16*kv + lq + 8*(quad&1))*PITCH + 16*(quad>>1));
            #pragma unroll
            for(int jp=0;jp<4;jp++){
                uint32_t vh4[4];
                LDM4T(vh4, vbase + jp*32);
                MMAB(oacc[2*jp],   pa, vh4[0], vh4[1]);
                MMAB(oacc[2*jp+1], pa, vh4[2], vh4[3]);
            }
        }
        if(++st==3) st=0;
    }

    float inv0=1.f/l0, inv1=1.f/l1;
    long long orow0 = (long long)zb*SD + (long long)(q0+r0l)*DMODEL + zh*64;
    long long orow1 = orow0 + 8LL*DMODEL;
    #pragma unroll
    for(int d=0;d<8;d++){
        int col = d*8 + 2*(lane&3);
        *(uint32_t*)(ch+orow0+col)=pack2h(oacc[d][0]*inv0, oacc[d][1]*inv0);
        *(uint32_t*)(ch+orow1+col)=pack2h(oacc[d][2]*inv1, oacc[d][3]*inv1);
    }
}

// ---------------- support kernels ----------------
__global__ void maskflag_k(const int* __restrict__ mask, unsigned char* __restrict__ flag){
    __shared__ int ok;
    if(threadIdx.x==0) ok=1;
    __syncthreads();
    int ty = blockIdx.x>>4, tx = blockIdx.x&15;
    int row = ty*128 + (threadIdx.x>>1);
    int c0  = tx*128 + (threadIdx.x&1)*64;
    const int4* p = (const int4*)&mask[(long long)row*SSEQ + c0];
    int good = 1;
    #pragma unroll
    for(int i=0;i<16;i++){
        int4 v = p[i];
        good &= (v.x!=0)&(v.y!=0)&(v.z!=0)&(v.w!=0);
    }
    if(!good) atomicAnd(&ok, 0);
    __syncthreads();
    if(threadIdx.x==0) flag[blockIdx.x]=(unsigned char)ok;
}
__global__ void cvt_h(const float* __restrict__ in, hf* __restrict__ hi, int n4){
    int i=blockIdx.x*blockDim.x+threadIdx.x; if(i>=n4)return;
    float4 v=((const float4*)in)[i];
    ((uint32_t*)hi)[2*i]  =pack2h(v.x,v.y);
    ((uint32_t*)hi)[2*i+1]=pack2h(v.z,v.w);
}
__global__ void split_T4(const float* __restrict__ W0,const float* __restrict__ W1,
                         const float* __restrict__ W2,const float* __restrict__ W3,
                         hf* __restrict__ H0,hf* __restrict__ H1,
                         hf* __restrict__ H2,hf* __restrict__ H3){
    const float* W = (blockIdx.z==0)?W0:(blockIdx.z==1)?W1:(blockIdx.z==2)?W2:W3;
    hf* H = (blockIdx.z==0)?H0:(blockIdx.z==1)?H1:(blockIdx.z==2)?H2:H3;
    __shared__ float t[32][33];
    int c0=blockIdx.x*32, r0=blockIdx.y*32, tx=threadIdx.x, ty=threadIdx.y;
    for(int i=ty;i<32;i+=8) t[i][tx]=W[(long long)(r0+i)*DMODEL+c0+tx];
    __syncthreads();
    for(int i=ty;i<32;i+=8)
        H[(long long)(c0+i)*DMODEL+r0+tx]=__float2half_rn(t[tx][i]);
}
__global__ void split_T(const float* __restrict__ W, hf* __restrict__ hi, int R, int C){
    __shared__ float t[32][33];
    int c0=blockIdx.x*32, r0=blockIdx.y*32, tx=threadIdx.x, ty=threadIdx.y;
    for(int i=ty;i<32;i+=8) t[i][tx]=W[(long long)(r0+i)*C+c0+tx];
    __syncthreads();
    for(int i=ty;i<32;i+=8)
        hi[(long long)(c0+i)*R+r0+tx]=__float2half_rn(t[tx][i]);
}
__global__ void gatek(const hf* __restrict__ qh,
                      const float* __restrict__ gW,const float* __restrict__ gb,
                      float* __restrict__ gate){
    int warp=(blockIdx.x*blockDim.x+threadIdx.x)>>5, lane=threadIdx.x&31;
    if(warp>=ROWS*NHEADS)return;
    int bs=warp>>4,h=warp&15;
    long long base=(long long)bs*DMODEL+h*DKH;
    float q0=__half2float(qh[base+lane]);
    float q1=__half2float(qh[base+lane+32]);
    float s=q0*gW[lane]+q1*gW[lane+32];
    #pragma unroll
    for(int o=16;o;o>>=1)s+=__shfl_xor_sync(~0u,s,o);
    if(lane==0){int b=bs>>11,sr=bs&2047;
        gate[(long long)(b*NHEADS+h)*SSEQ+sr]=1.f/(1.f+expf(-(s+gb[0])));}
}
__device__ __forceinline__ float wSum(float v){
    #pragma unroll
    for(int o=16;o;o>>=1)v+=__shfl_xor_sync(~0u,v,o); return v;}

__global__ void __launch_bounds__(256) layernorm_k(const float* __restrict__ a,
    const float* __restrict__ resid, const float* __restrict__ g, const float* __restrict__ b,
    float* __restrict__ outf, hf* __restrict__ oh){
    long long row=blockIdx.x;
    const float* pa=a+row*DMODEL;
    const float* pr=resid?resid+row*DMODEL:nullptr;
    int t=threadIdx.x,lane=t&31,wid=t>>5;
    __shared__ float s1[8],s2a[8]; __shared__ float bm,brs;
    float v[4],s=0.f,s2=0.f;
    #pragma unroll
    for(int i=0;i<4;i++){int d=t+i*256;float x=pa[d]+(pr?pr[d]:0.f);v[i]=x;s+=x;s2+=x*x;}
    s=wSum(s);s2=wSum(s2);
    if(lane==0){s1[wid]=s;s2a[wid]=s2;} __syncthreads();
    if(wid==0){float xs=(lane<8)?s1[lane]:0.f,x2=(lane<8)?s2a[lane]:0.f;
        xs=wSum(xs);x2=wSum(x2);
        if(lane==0){float mean=xs*(1.f/DMODEL);float var=fmaxf(x2*(1.f/DMODEL)-mean*mean,0.f);
            bm=mean;brs=rsqrtf(var+1e-5f);}}
    __syncthreads();
    float mean=bm,rstd=brs;
    #pragma unroll
    for(int i=0;i<4;i++){int d=t+i*256;float y=(v[i]-mean)*rstd*g[d]+b[d];
        if(outf)outf[row*DMODEL+d]=y;
        if(oh)oh[row*DMODEL+d]=__float2half_rn(y);}
}

__global__ void __launch_bounds__(256) layernorm2_k(const float* __restrict__ t0,
    const float* __restrict__ x,
    const float* __restrict__ lag, const float* __restrict__ lab,
    const float* __restrict__ n1g, const float* __restrict__ n1b,
    float* __restrict__ x1, hf* __restrict__ oh){
    long long row=blockIdx.x;
    const float* pa=t0+row*DMODEL;
    const float* px=x+row*DMODEL;
    int t=threadIdx.x,lane=t&31,wid=t>>5;
    __shared__ float s1[8],s2a[8]; __shared__ float bm,brs;
    float v[4],s=0.f,s2=0.f;
    #pragma unroll
    for(int i=0;i<4;i++){int d=t+i*256;float xx=pa[d];v[i]=xx;s+=xx;s2+=xx*xx;}
    s=wSum(s);s2=wSum(s2);
    if(lane==0){s1[wid]=s;s2a[wid]=s2;} __syncthreads();
    if(wid==0){float xs=(lane<8)?s1[lane]:0.f,x2=(lane<8)?s2a[lane]:0.f;
        xs=wSum(xs);x2=wSum(x2);
        if(lane==0){float mean=xs*(1.f/DMODEL);float var=fmaxf(x2*(1.f/DMODEL)-mean*mean,0.f);
            bm=mean;brs=rsqrtf(var+1e-5f);}}
    __syncthreads();
    float mean=bm,rstd=brs;
    s=0.f; s2=0.f;
    #pragma unroll
    for(int i=0;i<4;i++){int d=t+i*256;
        float y=(v[i]-mean)*rstd*lag[d]+lab[d] + px[d];
        v[i]=y; s+=y; s2+=y*y;}
    __syncthreads();
    s=wSum(s);s2=wSum(s2);
    if(lane==0){s1[wid]=s;s2a[wid]=s2;} __syncthreads();
    if(wid==0){float xs=(lane<8)?s1[lane]:0.f,x2=(lane<8)?s2a[lane]:0.f;
        xs=wSum(xs);x2=wSum(x2);
        if(lane==0){float mean2=xs*(1.f/DMODEL);float var=fmaxf(x2*(1.f/DMODEL)-mean2*mean2,0.f);
            bm=mean2;brs=rsqrtf(var+1e-5f);}}
    __syncthreads();
    mean=bm; rstd=brs;
    #pragma unroll
    for(int i=0;i<4;i++){int d=t+i*256;
        float y=(v[i]-mean)*rstd*n1g[d]+n1b[d];
        x1[row*DMODEL+d]=y;
        oh[row*DMODEL+d]=__float2half_rn(y);}
}

// ---------------- launch ----------------
extern "C" void kernel_launch(void* const* d_in, const int* in_sizes, int n_in,
                              void* d_out, int out_size)
{
    const float* x   =(const float*)d_in[0];
    const int*  mask =(const int*)  d_in[1];
    const float* Wq=(const float*)d_in[2],  *bq=(const float*)d_in[3];
    const float* Wk=(const float*)d_in[4],  *bk=(const float*)d_in[5];
    const float* Wv=(const float*)d_in[6],  *bv=(const float*)d_in[7];
    const float* Wo=(const float*)d_in[8],  *bo=(const float*)d_in[9];
    const float* temp=(const float*)d_in[10], *tw=(const float*)d_in[11];
    const float* gW=(const float*)d_in[12], *gb=(const float*)d_in[13];
    const float* lag=(const float*)d_in[14],*lab=(const float*)d_in[15];
    const float* f1W=(const float*)d_in[16],*f1b=(const float*)d_in[17];
    const float* f2W=(const float*)d_in[18],*f2b=(const float*)d_in[19];
    const float* n1g=(const float*)d_in[20],*n1b=(const float*)d_in[21];
    const float* n2g=(const float*)d_in[22],*n2b=(const float*)d_in[23];
    float* out=(float*)d_out;

    float *t0,*x1,*gatep;
    unsigned char* mflag;
    hf *xh,*qh,*kh,*vh,*ch,*yh,*fh;
    hf *wqh,*wkh,*wvh,*woh,*w1h,*w2h;
    cudaGetSymbolAddress((void**)&t0,g_t0);   cudaGetSymbolAddress((void**)&x1,g_x1);
    cudaGetSymbolAddress((void**)&gatep,g_gate);
    cudaGetSymbolAddress((void**)&mflag,g_mflag);
    cudaGetSymbolAddress((void**)&xh,g_xh);
    cudaGetSymbolAddress((void**)&qh,g_qh); cudaGetSymbolAddress((void**)&kh,g_kh);
    cudaGetSymbolAddress((void**)&vh,g_vh); cudaGetSymbolAddress((void**)&ch,g_ch);
    cudaGetSymbolAddress((void**)&yh,g_yh); cudaGetSymbolAddress((void**)&fh,g_fh);
    cudaGetSymbolAddress((void**)&wqh,g_wqh); cudaGetSymbolAddress((void**)&wkh,g_wkh);
    cudaGetSymbolAddress((void**)&wvh,g_wvh); cudaGetSymbolAddress((void**)&woh,g_woh);
    cudaGetSymbolAddress((void**)&w1h,g_w1h); cudaGetSymbolAddress((void**)&w2h,g_w2h);

    const int SMG = 3*15360;                   // 46080
    const int SMF = 18432 + 3*36864;           // 129024
    cudaFuncSetAttribute((const void*)hgemm,    cudaFuncAttributeMaxDynamicSharedMemorySize,SMG);
    cudaFuncSetAttribute((const void*)hgemm3,   cudaFuncAttributeMaxDynamicSharedMemorySize,SMG);
    cudaFuncSetAttribute((const void*)flashattn,cudaFuncAttributeMaxDynamicSharedMemorySize,SMF);

    dim3 tb(32,8);
    cvt_h<<<ROWS*DMODEL/4/256,256>>>(x,xh,ROWS*DMODEL/4);
    maskflag_k<<<256,256>>>(mask,mflag);
    split_T4<<<dim3(DMODEL/32,DMODEL/32,4),tb>>>(Wq,Wk,Wv,Wo,wqh,wkh,wvh,woh);

    // fused Q/K/V projections (CTA tile 64x128)
    dim3 gP3(DMODEL/128,ROWS/64,3);
    hgemm3<<<gP3,256,SMG>>>(xh,wqh,wkh,wvh,qh,kh,vh,bq,bk,bv,tw);

    gatek<<<(ROWS*NHEADS)/8,256>>>(qh,gW,gb,gatep);

    dim3 gA(SSEQ/128, ZTOT, 1);
    flashattn<<<gA,256,SMF>>>(qh,kh,vh,mask,mflag,gatep,temp,ch);

    dim3 gP(DMODEL/128,ROWS/64,1);
    hgemm<<<gP,256,SMG>>>(ch,woh,DMODEL,DMODEL,DMODEL,DMODEL,
        t0,nullptr,bo,nullptr,0,0);
    layernorm2_k<<<ROWS,256>>>(t0,x,lag,lab,n1g,n1b,x1,yh);

    split_T<<<dim3(DFF/32,DMODEL/32),tb>>>(f1W,w1h,DMODEL,DFF);
    split_T<<<dim3(DMODEL/32,DFF/32),tb>>>(f2W,w2h,DFF,DMODEL);

    dim3 gF(DFF/128,ROWS/64,1);
    hgemm<<<gF,256,SMG>>>(yh,w1h,DMODEL,DMODEL,DMODEL,DFF,
        nullptr,fh,f1b,nullptr,1,1);
    hgemm<<<gP,256,SMG>>>(fh,w2h,DFF,DFF,DFF,DMODEL,
        t0,nullptr,f2b,nullptr,0,0);

    layernorm_k<<<ROWS,256>>>(x1,t0,n2g,n2b,out,nullptr);
}

// round 13
// speedup vs baseline: 1.1796x; 1.1796x over previous
#include <cuda_runtime.h>
#include <cuda_fp16.h>
#include <math.h>
#include <stdint.h>

#define SSEQ 2048
#define DMODEL 1024
#define NHEADS 16
#define DKH 64
#define DFF 4096
#define ROWS 4096
#define ZTOT 32
#define SD ((long long)SSEQ*DMODEL)
typedef __half hf;

// ---------------- scratch ----------------
__device__ __align__(256) float g_t0[ROWS*DMODEL];
__device__ __align__(256) float g_x1[ROWS*DMODEL];
__device__ __align__(256) float g_gate[ZTOT*SSEQ];
__device__ __align__(256) unsigned char g_mflag[256];
__device__ __align__(256) hf g_xh[ROWS*DMODEL];
__device__ __align__(256) hf g_qh[ROWS*DMODEL];
__device__ __align__(256) hf g_kh[ROWS*DMODEL];
__device__ __align__(256) hf g_vh[ROWS*DMODEL];
__device__ __align__(256) hf g_ch[ROWS*DMODEL];
__device__ __align__(256) hf g_yh[ROWS*DMODEL];
__device__ __align__(256) hf g_fh[ROWS*DFF];
__device__ __align__(256) hf g_wqh[DMODEL*DMODEL];   // [K,N] native layout, fp16
__device__ __align__(256) hf g_wkh[DMODEL*DMODEL];
__device__ __align__(256) hf g_wvh[DMODEL*DMODEL];
__device__ __align__(256) hf g_woh[DMODEL*DMODEL];
__device__ __align__(256) hf g_w1h[DMODEL*DFF];
__device__ __align__(256) hf g_w2h[DFF*DMODEL];

// ---------------- helpers ----------------
__device__ __forceinline__ uint32_t su32(const void* p){uint32_t a;
    asm("{.reg .u64 t; cvta.to.shared.u64 t,%1; cvt.u32.u64 %0,t;}":"=r"(a):"l"(p));return a;}
__device__ __forceinline__ void cpa(uint32_t d,const void*s){
    asm volatile("cp.async.cg.shared.global [%0],[%1],16;"::"r"(d),"l"(s));}
#define CPCOMMIT() asm volatile("cp.async.commit_group;":::"memory")
#define LDM4(f,a) asm volatile("ldmatrix.sync.aligned.m8n8.x4.shared.b16 {%0,%1,%2,%3},[%4];" \
    :"=r"((f)[0]),"=r"((f)[1]),"=r"((f)[2]),"=r"((f)[3]):"r"(a))
#define LDM4B(b0,b1,b2,b3,a) asm volatile("ldmatrix.sync.aligned.m8n8.x4.shared.b16 {%0,%1,%2,%3},[%4];" \
    :"=r"(b0),"=r"(b1),"=r"(b2),"=r"(b3):"r"(a))
#define LDM4T(f,a) asm volatile("ldmatrix.sync.aligned.m8n8.x4.trans.shared.b16 {%0,%1,%2,%3},[%4];" \
    :"=r"((f)[0]),"=r"((f)[1]),"=r"((f)[2]),"=r"((f)[3]):"r"(a))
#define MMA(c,A,B) asm volatile( \
    "mma.sync.aligned.m16n8k16.row.col.f32.f16.f16.f32 {%0,%1,%2,%3},{%4,%5,%6,%7},{%8,%9},{%0,%1,%2,%3};" \
    :"+f"((c)[0]),"+f"((c)[1]),"+f"((c)[2]),"+f"((c)[3]) \
    :"r"((A)[0]),"r"((A)[1]),"r"((A)[2]),"r"((A)[3]),"r"((B)[0]),"r"((B)[1]))
#define MMAB(c,A,b0,b1) asm volatile( \
    "mma.sync.aligned.m16n8k16.row.col.f32.f16.f16.f32 {%0,%1,%2,%3},{%4,%5,%6,%7},{%8,%9},{%0,%1,%2,%3};" \
    :"+f"((c)[0]),"+f"((c)[1]),"+f"((c)[2]),"+f"((c)[3]) \
    :"r"((A)[0]),"r"((A)[1]),"r"((A)[2]),"r"((A)[3]),"r"(b0),"r"(b1))

__device__ __forceinline__ uint32_t pack2h(float a, float b){
    __half2 hp=__floats2half2_rn(a,b);
    return *(uint32_t*)&hp;
}

// ---------------- fp16 HMMA GEMM, trans-B (weights in native [K,N]) -------
// CTA tile 128x128, warp 64x32 (8 warps: 2M x 4N), BK=64 per barrier,
// 3-stage cp.async ring, 2 CTAs/SM.
// A [M,K] row-major; B [K,N] row-major; C = A @ B.
#define APITCH 144
#define BPITCH 272
__device__ __forceinline__ void hgemm_body(
    const hf* __restrict__ A_, const hf* __restrict__ B_,
    int K, int lda, int ldb, int ldc,
    float* __restrict__ Cf, hf* __restrict__ Ch,
    const float* __restrict__ bias, const float* __restrict__ bias2,
    int epi, int outm)
{
    constexpr int ABYTES = 128*APITCH;        // 18432
    constexpr int STG    = ABYTES + 64*BPITCH; // 35840
    extern __shared__ char smraw[];
    uint32_t su = su32(smraw);
    int tid = threadIdx.x, wid = tid>>5, lane = tid&31;
    int wm = wid%2, wn = wid/2;
    int m0 = blockIdx.y*128, n0 = blockIdx.x*128;

    const hf* pA = A_ + (long long)m0*lda;
    const hf* pB = B_ + n0;
    int nk = K>>6;

    // A: 128 rows x 128B (8 chunks); B: 64 rows x 256B (16 chunks)
    int ar = tid>>1, ac = tid&1;        // A: 2 passes x (row, 4-chunk group)? use c-index math below
    auto loadstage = [&](int ci, int st){
        uint32_t b = su + (uint32_t)st*STG;
        int k0 = ci<<6;
        #pragma unroll
        for(int p=0;p<4;p++){
            int c = tid + p*256;        // 0..1023 A chunks
            int row = c>>3, col = c&7;
            cpa(b + row*APITCH + col*16, pA + (long long)row*lda + k0 + col*8);
        }
        #pragma unroll
        for(int p=0;p<4;p++){
            int c = tid + p*256;        // 0..1023 B chunks
            int row = c>>4, col = c&15;
            cpa(b + ABYTES + row*BPITCH + col*16, pB + (long long)(k0+row)*ldb + col*8);
        }
        CPCOMMIT();
    };
    (void)ar;(void)ac;

    float acc[4][4][4];
    #pragma unroll
    for(int a=0;a<4;a++)
        #pragma unroll
        for(int b=0;b<4;b++)
            #pragma unroll
            for(int c=0;c<4;c++) acc[a][b][c]=0.f;

    int quad = lane>>3, lq = lane&7;
    uint32_t aoff = (uint32_t)((wm*64 + (quad&1)*8 + lq)*APITCH + (quad>>1)*16);
    uint32_t boff = (uint32_t)(ABYTES + (lq + 8*(quad&1))*BPITCH + wn*64 + 16*(quad>>1));

    loadstage(0,0);
    if(nk>1) loadstage(1,1);

    int st = 0;
    for(int i=0;i<nk;i++){
        if(i+1<nk) asm volatile("cp.async.wait_group 1;":::"memory");
        else       asm volatile("cp.async.wait_group 0;":::"memory");
        __syncthreads();
        if(i+2<nk){
            int st2 = st+2; if(st2>=3) st2-=3;
            loadstage(i+2, st2);
        }
        uint32_t sb = su + (uint32_t)st*STG;
        uint32_t pa = sb + aoff, pb = sb + boff;
        #pragma unroll
        for(int ks=0;ks<4;ks++){                 // 4 x k16 groups
            uint32_t Af[4][4];
            #pragma unroll
            for(int mt=0;mt<4;mt++) LDM4(Af[mt], pa + mt*(16*APITCH) + ks*32);
            #pragma unroll
            for(int jp=0;jp<2;jp++){
                uint32_t bt[4];
                LDM4T(bt, pb + ks*(16*BPITCH) + jp*32);
                #pragma unroll
                for(int mt=0;mt<4;mt++){
                    MMAB(acc[mt][2*jp],   Af[mt], bt[0], bt[1]);
                    MMAB(acc[mt][2*jp+1], Af[mt], bt[2], bt[3]);
                }
            }
        }
        if(++st==3) st=0;
    }

    auto store2 = [&](int row,int col,float v0,float v1){
        if(bias){ v0+=bias[col]; v1+=bias[col+1]; }
        if(bias2){ v0+=bias2[col]; v1+=bias2[col+1]; }
        if(epi==1){
            v0 = 0.5f*v0*(1.0f+erff(v0*0.70710678118654752f));
            v1 = 0.5f*v1*(1.0f+erff(v1*0.70710678118654752f));
        }
        if(outm==0){
            *(float2*)&Cf[(long long)row*ldc+col] = make_float2(v0,v1);
        } else {
            *(uint32_t*)(Ch+(long long)row*ldc+col) = pack2h(v0,v1);
        }
    };
    #pragma unroll
    for(int mt=0;mt<4;mt++){
        #pragma unroll
        for(int nt=0;nt<4;nt++){
            int row0 = m0 + wm*64 + mt*16 + (lane>>2);
            int col  = n0 + wn*32 + nt*8 + ((lane&3)<<1);
            store2(row0,   col, acc[mt][nt][0], acc[mt][nt][1]);
            store2(row0+8, col, acc[mt][nt][2], acc[mt][nt][3]);
        }
    }
}

__global__ __launch_bounds__(256,2) void hgemm(
    const hf* __restrict__ A_, const hf* __restrict__ B_,
    int K, int lda, int ldb, int ldc,
    float* __restrict__ Cf, hf* __restrict__ Ch,
    const float* __restrict__ bias, const float* __restrict__ bias2,
    int epi, int outm)
{
    hgemm_body(A_,B_,K,lda,ldb,ldc,Cf,Ch,bias,bias2,epi,outm);
}

__global__ __launch_bounds__(256,2) void hgemm3(
    const hf* __restrict__ A_,
    const hf* __restrict__ Bq, const hf* __restrict__ Bk, const hf* __restrict__ Bv,
    hf* __restrict__ Cq, hf* __restrict__ Ck, hf* __restrict__ Cv,
    const float* __restrict__ bq, const float* __restrict__ bk, const float* __restrict__ bv,
    const float* __restrict__ tw)
{
    int z = blockIdx.z;
    const hf* B = (z==0)?Bq:(z==1)?Bk:Bv;
    hf* C = (z==0)?Cq:(z==1)?Ck:Cv;
    const float* bias = (z==0)?bq:(z==1)?bk:bv;
    const float* bias2 = (z==0)?tw:nullptr;
    hgemm_body(A_,B,DMODEL,DMODEL,DMODEL,DMODEL,nullptr,C,bias,bias2,0,1);
}

// ---------------- flash attention (unchanged from R11) ----------------
#define PITCH 144
__global__ __launch_bounds__(256,1) void flashattn(
    const hf* __restrict__ qh_, const hf* __restrict__ kh_, const hf* __restrict__ vh_,
    const int* __restrict__ mask, const unsigned char* __restrict__ mflag,
    const float* __restrict__ gate,
    const float* __restrict__ temp, hf* __restrict__ ch)
{
    extern __shared__ char sm[];
    uint32_t su = su32(sm);
    const uint32_t ST=18432, STSZ=36864;
    int tid=threadIdx.x, wid=tid>>5, lane=tid&31;
    int quad=lane>>3, lq=lane&7;
    int z=blockIdx.y, zb=z>>4, zh=z&15;
    int q0=blockIdx.x*128;
    long long hoff=(long long)zb*SD + zh*64;
    const hf* pq = qh_ + hoff + (long long)q0*DMODEL;

    int cc=tid&7, rr0=tid>>3;
    #pragma unroll
    for(int p=0;p<4;p++){
        int r=rr0+p*32;
        cpa(su + r*PITCH + cc*16, pq + (long long)r*DMODEL + cc*8);
    }
    CPCOMMIT();

    auto ldstage=[&](int it,int st){
        uint32_t b=su+ST+(uint32_t)st*STSZ;
        long long kbase=hoff + (long long)(it*128)*DMODEL;
        #pragma unroll
        for(int p=0;p<4;p++){
            int r=rr0+p*32;
            long long go=kbase+(long long)r*DMODEL+cc*8;
            uint32_t so=r*PITCH+cc*16;
            cpa(b+so, kh_+go);
            cpa(b+18432+so, vh_+go);
        }
        CPCOMMIT();
    };
    ldstage(0,0); ldstage(1,1);
    asm volatile("cp.async.wait_group 2;":::"memory");
    __syncthreads();

    uint32_t qaddr = su + (uint32_t)((wid*16 + (quad&1)*8 + lq)*PITCH + (quad>>1)*16);
    uint32_t qf[4][4];
    #pragma unroll
    for(int ks=0;ks<4;ks++) LDM4(qf[ks], qaddr+ks*32);

    int r0l = wid*16 + (lane>>2);
    float g0 = gate[(long long)z*SSEQ + q0 + r0l];
    float g1 = gate[(long long)z*SSEQ + q0 + r0l + 8];
    float invT = 1.f/temp[0];
    float m0=-1e30f,m1=-1e30f,l0=0.f,l1=0.f;
    float oacc[8][4];
    #pragma unroll
    for(int d=0;d<8;d++){oacc[d][0]=0;oacc[d][1]=0;oacc[d][2]=0;oacc[d][3]=0;}

    int st = 0;
    for(int it=0; it<16; it++){
        if(it<15) asm volatile("cp.async.wait_group 1;":::"memory");
        else      asm volatile("cp.async.wait_group 0;":::"memory");
        __syncthreads();
        if(it+2<16){
            int st2 = st+2; if(st2>=3) st2-=3;
            ldstage(it+2, st2);
        }
        uint32_t sb = su+ST+(uint32_t)st*STSZ;

        float sacc[16][4];
        #pragma unroll
        for(int nt=0;nt<16;nt++){sacc[nt][0]=0;sacc[nt][1]=0;sacc[nt][2]=0;sacc[nt][3]=0;}
        uint32_t baddr = sb + (uint32_t)((lq + 8*(quad>>1))*PITCH + (quad&1)*16);
        #pragma unroll
        for(int ks=0;ks<4;ks++){
            uint32_t b[16][2];
            #pragma unroll
            for(int j=0;j<8;j++)
                LDM4B(b[2*j][0],b[2*j][1],b[2*j+1][0],b[2*j+1][1], baddr + j*(16*PITCH) + ks*32);
            #pragma unroll
            for(int nt=0;nt<16;nt++) MMA(sacc[nt], qf[ks], b[nt]);
        }

        float rm0=-1e30f, rm1=-1e30f;
        if(mflag[(q0>>7)*16 + it]){
            #pragma unroll
            for(int nt=0;nt<16;nt++){
                float s0=sacc[nt][0]*invT, s1=sacc[nt][1]*invT;
                float s2=sacc[nt][2]*invT, s3=sacc[nt][3]*invT;
                s0*=g0;s1*=g0;s2*=g1;s3*=g1;
                sacc[nt][0]=s0;sacc[nt][1]=s1;sacc[nt][2]=s2;sacc[nt][3]=s3;
                rm0=fmaxf(rm0,fmaxf(s0,s1)); rm1=fmaxf(rm1,fmaxf(s2,s3));
            }
        } else {
            long long mrow0 = (long long)(q0 + r0l)*SSEQ + it*128 + 2*(lane&3);
            long long mrow1 = mrow0 + 8LL*SSEQ;
            #pragma unroll
            for(int nt=0;nt<16;nt++){
                int2 mA = *(const int2*)&mask[mrow0 + nt*8];
                int2 mB = *(const int2*)&mask[mrow1 + nt*8];
                float s0=sacc[nt][0]*invT, s1=sacc[nt][1]*invT;
                float s2=sacc[nt][2]*invT, s3=sacc[nt][3]*invT;
                if(mA.x==0)s0=-1e9f; if(mA.y==0)s1=-1e9f;
                if(mB.x==0)s2=-1e9f; if(mB.y==0)s3=-1e9f;
                s0*=g0;s1*=g0;s2*=g1;s3*=g1;
                sacc[nt][0]=s0;sacc[nt][1]=s1;sacc[nt][2]=s2;sacc[nt][3]=s3;
                rm0=fmaxf(rm0,fmaxf(s0,s1)); rm1=fmaxf(rm1,fmaxf(s2,s3));
            }
        }
        rm0=fmaxf(rm0,__shfl_xor_sync(~0u,rm0,1)); rm0=fmaxf(rm0,__shfl_xor_sync(~0u,rm0,2));
        rm1=fmaxf(rm1,__shfl_xor_sync(~0u,rm1,1)); rm1=fmaxf(rm1,__shfl_xor_sync(~0u,rm1,2));
        float mn0=fmaxf(m0,rm0), mn1=fmaxf(m1,rm1);
        float sc0=__expf(m0-mn0), sc1=__expf(m1-mn1);
        m0=mn0; m1=mn1;

        float rs0=0.f, rs1=0.f;
        #pragma unroll
        for(int nt=0;nt<16;nt++){
            float p0=__expf(sacc[nt][0]-m0), p1=__expf(sacc[nt][1]-m0);
            float p2=__expf(sacc[nt][2]-m1), p3=__expf(sacc[nt][3]-m1);
            sacc[nt][0]=p0;sacc[nt][1]=p1;sacc[nt][2]=p2;sacc[nt][3]=p3;
            rs0+=p0+p1; rs1+=p2+p3;
        }
        rs0+=__shfl_xor_sync(~0u,rs0,1); rs0+=__shfl_xor_sync(~0u,rs0,2);
        rs1+=__shfl_xor_sync(~0u,rs1,1); rs1+=__shfl_xor_sync(~0u,rs1,2);
        l0 = l0*sc0 + rs0; l1 = l1*sc1 + rs1;
        #pragma unroll
        for(int d=0;d<8;d++){ oacc[d][0]*=sc0; oacc[d][1]*=sc0; oacc[d][2]*=sc1; oacc[d][3]*=sc1; }

        #pragma unroll
        for(int kv=0;kv<8;kv++){
            uint32_t pa[4];
            pa[0]=pack2h(sacc[2*kv][0],   sacc[2*kv][1]);
            pa[1]=pack2h(sacc[2*kv][2],   sacc[2*kv][3]);
            pa[2]=pack2h(sacc[2*kv+1][0], sacc[2*kv+1][1]);
            pa[3]=pack2h(sacc[2*kv+1][2], sacc[2*kv+1][3]);
            uint32_t vbase = sb + 18432 + (uint32_t)((16*kv + lq + 8*(quad&1))*PITCH + 16*(quad>>1));
            #pragma unroll
            for(int jp=0;jp<4;jp++){
                uint32_t vh4[4];
                LDM4T(vh4, vbase + jp*32);
                MMAB(oacc[2*jp],   pa, vh4[0], vh4[1]);
                MMAB(oacc[2*jp+1], pa, vh4[2], vh4[3]);
            }
        }
        if(++st==3) st=0;
    }

    float inv0=1.f/l0, inv1=1.f/l1;
    long long orow0 = (long long)zb*SD + (long long)(q0+r0l)*DMODEL + zh*64;
    long long orow1 = orow0 + 8LL*DMODEL;
    #pragma unroll
    for(int d=0;d<8;d++){
        int col = d*8 + 2*(lane&3);
        *(uint32_t*)(ch+orow0+col)=pack2h(oacc[d][0]*inv0, oacc[d][1]*inv0);
        *(uint32_t*)(ch+orow1+col)=pack2h(oacc[d][2]*inv1, oacc[d][3]*inv1);
    }
}

// ---------------- support kernels ----------------
__global__ void maskflag_k(const int* __restrict__ mask, unsigned char* __restrict__ flag){
    __shared__ int ok;
    if(threadIdx.x==0) ok=1;
    __syncthreads();
    int ty = blockIdx.x>>4, tx = blockIdx.x&15;
    int row = ty*128 + (threadIdx.x>>1);
    int c0  = tx*128 + (threadIdx.x&1)*64;
    const int4* p = (const int4*)&mask[(long long)row*SSEQ + c0];
    int good = 1;
    #pragma unroll
    for(int i=0;i<16;i++){
        int4 v = p[i];
        good &= (v.x!=0)&(v.y!=0)&(v.z!=0)&(v.w!=0);
    }
    if(!good) atomicAnd(&ok, 0);
    __syncthreads();
    if(threadIdx.x==0) flag[blockIdx.x]=(unsigned char)ok;
}
__global__ void cvt_h(const float* __restrict__ in, hf* __restrict__ hi, int n4){
    int i=blockIdx.x*blockDim.x+threadIdx.x; if(i>=n4)return;
    float4 v=((const float4*)in)[i];
    ((uint32_t*)hi)[2*i]  =pack2h(v.x,v.y);
    ((uint32_t*)hi)[2*i+1]=pack2h(v.z,v.w);
}
// convert 4 attention weight matrices (no transpose; native [K,N])
__global__ void cvt4w(const float* __restrict__ W0,const float* __restrict__ W1,
                      const float* __restrict__ W2,const float* __restrict__ W3,
                      hf* __restrict__ H0,hf* __restrict__ H1,
                      hf* __restrict__ H2,hf* __restrict__ H3, int n4){
    const float* W=(blockIdx.y==0)?W0:(blockIdx.y==1)?W1:(blockIdx.y==2)?W2:W3;
    hf* H=(blockIdx.y==0)?H0:(blockIdx.y==1)?H1:(blockIdx.y==2)?H2:H3;
    int i=blockIdx.x*blockDim.x+threadIdx.x; if(i>=n4)return;
    float4 v=((const float4*)W)[i];
    ((uint32_t*)H)[2*i]  =pack2h(v.x,v.y);
    ((uint32_t*)H)[2*i+1]=pack2h(v.z,v.w);
}
__global__ void gatek(const hf* __restrict__ qh,
                      const float* __restrict__ gW,const float* __restrict__ gb,
                      float* __restrict__ gate){
    int warp=(blockIdx.x*blockDim.x+threadIdx.x)>>5, lane=threadIdx.x&31;
    if(warp>=ROWS*NHEADS)return;
    int bs=warp>>4,h=warp&15;
    long long base=(long long)bs*DMODEL+h*DKH;
    float q0=__half2float(qh[base+lane]);
    float q1=__half2float(qh[base+lane+32]);
    float s=q0*gW[lane]+q1*gW[lane+32];
    #pragma unroll
    for(int o=16;o;o>>=1)s+=__shfl_xor_sync(~0u,s,o);
    if(lane==0){int b=bs>>11,sr=bs&2047;
        gate[(long long)(b*NHEADS+h)*SSEQ+sr]=1.f/(1.f+expf(-(s+gb[0])));}
}
__device__ __forceinline__ float wSum(float v){
    #pragma unroll
    for(int o=16;o;o>>=1)v+=__shfl_xor_sync(~0u,v,o); return v;}

__global__ void __launch_bounds__(256) layernorm_k(const float* __restrict__ a,
    const float* __restrict__ resid, const float* __restrict__ g, const float* __restrict__ b,
    float* __restrict__ outf, hf* __restrict__ oh){
    long long row=blockIdx.x;
    const float* pa=a+row*DMODEL;
    const float* pr=resid?resid+row*DMODEL:nullptr;
    int t=threadIdx.x,lane=t&31,wid=t>>5;
    __shared__ float s1[8],s2a[8]; __shared__ float bm,brs;
    float v[4],s=0.f,s2=0.f;
    #pragma unroll
    for(int i=0;i<4;i++){int d=t+i*256;float x=pa[d]+(pr?pr[d]:0.f);v[i]=x;s+=x;s2+=x*x;}
    s=wSum(s);s2=wSum(s2);
    if(lane==0){s1[wid]=s;s2a[wid]=s2;} __syncthreads();
    if(wid==0){float xs=(lane<8)?s1[lane]:0.f,x2=(lane<8)?s2a[lane]:0.f;
        xs=wSum(xs);x2=wSum(x2);
        if(lane==0){float mean=xs*(1.f/DMODEL);float var=fmaxf(x2*(1.f/DMODEL)-mean*mean,0.f);
            bm=mean;brs=rsqrtf(var+1e-5f);}}
    __syncthreads();
    float mean=bm,rstd=brs;
    #pragma unroll
    for(int i=0;i<4;i++){int d=t+i*256;float y=(v[i]-mean)*rstd*g[d]+b[d];
        if(outf)outf[row*DMODEL+d]=y;
        if(oh)oh[row*DMODEL+d]=__float2half_rn(y);}
}

__global__ void __launch_bounds__(256) layernorm2_k(const float* __restrict__ t0,
    const float* __restrict__ x,
    const float* __restrict__ lag, const float* __restrict__ lab,
    const float* __restrict__ n1g, const float* __restrict__ n1b,
    float* __restrict__ x1, hf* __restrict__ oh){
    long long row=blockIdx.x;
    const float* pa=t0+row*DMODEL;
    const float* px=x+row*DMODEL;
    int t=threadIdx.x,lane=t&31,wid=t>>5;
    __shared__ float s1[8],s2a[8]; __shared__ float bm,brs;
    float v[4],s=0.f,s2=0.f;
    #pragma unroll
    for(int i=0;i<4;i++){int d=t+i*256;float xx=pa[d];v[i]=xx;s+=xx;s2+=xx*xx;}
    s=wSum(s);s2=wSum(s2);
    if(lane==0){s1[wid]=s;s2a[wid]=s2;} __syncthreads();
    if(wid==0){float xs=(lane<8)?s1[lane]:0.f,x2=(lane<8)?s2a[lane]:0.f;
        xs=wSum(xs);x2=wSum(x2);
        if(lane==0){float mean=xs*(1.f/DMODEL);float var=fmaxf(x2*(1.f/DMODEL)-mean*mean,0.f);
            bm=mean;brs=rsqrtf(var+1e-5f);}}
    __syncthreads();
    float mean=bm,rstd=brs;
    s=0.f; s2=0.f;
    #pragma unroll
    for(int i=0;i<4;i++){int d=t+i*256;
        float y=(v[i]-mean)*rstd*lag[d]+lab[d] + px[d];
        v[i]=y; s+=y; s2+=y*y;}
    __syncthreads();
    s=wSum(s);s2=wSum(s2);
    if(lane==0){s1[wid]=s;s2a[wid]=s2;} __syncthreads();
    if(wid==0){float xs=(lane<8)?s1[lane]:0.f,x2=(lane<8)?s2a[lane]:0.f;
        xs=wSum(xs);x2=wSum(x2);
        if(lane==0){float mean2=xs*(1.f/DMODEL);float var=fmaxf(x2*(1.f/DMODEL)-mean2*mean2,0.f);
            bm=mean2;brs=rsqrtf(var+1e-5f);}}
    __syncthreads();
    mean=bm; rstd=brs;
    #pragma unroll
    for(int i=0;i<4;i++){int d=t+i*256;
        float y=(v[i]-mean)*rstd*n1g[d]+n1b[d];
        x1[row*DMODEL+d]=y;
        oh[row*DMODEL+d]=__float2half_rn(y);}
}

// ---------------- launch ----------------
extern "C" void kernel_launch(void* const* d_in, const int* in_sizes, int n_in,
                              void* d_out, int out_size)
{
    const float* x   =(const float*)d_in[0];
    const int*  mask =(const int*)  d_in[1];
    const float* Wq=(const float*)d_in[2],  *bq=(const float*)d_in[3];
    const float* Wk=(const float*)d_in[4],  *bk=(const float*)d_in[5];
    const float* Wv=(const float*)d_in[6],  *bv=(const float*)d_in[7];
    const float* Wo=(const float*)d_in[8],  *bo=(const float*)d_in[9];
    const float* temp=(const float*)d_in[10], *tw=(const float*)d_in[11];
    const float* gW=(const float*)d_in[12], *gb=(const float*)d_in[13];
    const float* lag=(const float*)d_in[14],*lab=(const float*)d_in[15];
    const float* f1W=(const float*)d_in[16],*f1b=(const float*)d_in[17];
    const float* f2W=(const float*)d_in[18],*f2b=(const float*)d_in[19];
    const float* n1g=(const float*)d_in[20],*n1b=(const float*)d_in[21];
    const float* n2g=(const float*)d_in[22],*n2b=(const float*)d_in[23];
    float* out=(float*)d_out;

    float *t0,*x1,*gatep;
    unsigned char* mflag;
    hf *xh,*qh,*kh,*vh,*ch,*yh,*fh;
    hf *wqh,*wkh,*wvh,*woh,*w1h,*w2h;
    cudaGetSymbolAddress((void**)&t0,g_t0);   cudaGetSymbolAddress((void**)&x1,g_x1);
    cudaGetSymbolAddress((void**)&gatep,g_gate);
    cudaGetSymbolAddress((void**)&mflag,g_mflag);
    cudaGetSymbolAddress((void**)&xh,g_xh);
    cudaGetSymbolAddress((void**)&qh,g_qh); cudaGetSymbolAddress((void**)&kh,g_kh);
    cudaGetSymbolAddress((void**)&vh,g_vh); cudaGetSymbolAddress((void**)&ch,g_ch);
    cudaGetSymbolAddress((void**)&yh,g_yh); cudaGetSymbolAddress((void**)&fh,g_fh);
    cudaGetSymbolAddress((void**)&wqh,g_wqh); cudaGetSymbolAddress((void**)&wkh,g_wkh);
    cudaGetSymbolAddress((void**)&wvh,g_wvh); cudaGetSymbolAddress((void**)&woh,g_woh);
    cudaGetSymbolAddress((void**)&w1h,g_w1h); cudaGetSymbolAddress((void**)&w2h,g_w2h);

    const int SMG = 3*35840;                   // 107520
    const int SMF = 18432 + 3*36864;           // 129024
    cudaFuncSetAttribute((const void*)hgemm,    cudaFuncAttributeMaxDynamicSharedMemorySize,SMG);
    cudaFuncSetAttribute((const void*)hgemm3,   cudaFuncAttributeMaxDynamicSharedMemorySize,SMG);
    cudaFuncSetAttribute((const void*)flashattn,cudaFuncAttributeMaxDynamicSharedMemorySize,SMF);

    cvt_h<<<ROWS*DMODEL/4/256,256>>>(x,xh,ROWS*DMODEL/4);
    maskflag_k<<<256,256>>>(mask,mflag);
    cvt4w<<<dim3(DMODEL*DMODEL/4/256,4),256>>>(Wq,Wk,Wv,Wo,wqh,wkh,wvh,woh,DMODEL*DMODEL/4);

    dim3 gP3(DMODEL/128,ROWS/128,3);
    hgemm3<<<gP3,256,SMG>>>(xh,wqh,wkh,wvh,qh,kh,vh,bq,bk,bv,tw);

    gatek<<<(ROWS*NHEADS)/8,256>>>(qh,gW,gb,gatep);

    dim3 gA(SSEQ/128, ZTOT, 1);
    flashattn<<<gA,256,SMF>>>(qh,kh,vh,mask,mflag,gatep,temp,ch);

    dim3 gP(DMODEL/128,ROWS/128,1);
    hgemm<<<gP,256,SMG>>>(ch,woh,DMODEL,DMODEL,DMODEL,DMODEL,
        t0,nullptr,bo,nullptr,0,0);
    layernorm2_k<<<ROWS,256>>>(t0,x,lag,lab,n1g,n1b,x1,yh);

    cvt_h<<<DMODEL*DFF/4/256,256>>>(f1W,w1h,DMODEL*DFF/4);
    cvt_h<<<DMODEL*DFF/4/256,256>>>(f2W,w2h,DMODEL*DFF/4);

    dim3 gF(DFF/128,ROWS/128,1);
    hgemm<<<gF,256,SMG>>>(yh,w1h,DMODEL,DMODEL,DFF,DFF,
        nullptr,fh,f1b,nullptr,1,1);
    hgemm<<<gP,256,SMG>>>(fh,w2h,DFF,DFF,DMODEL,DMODEL,
        t0,nullptr,f2b,nullptr,0,0);

    layernorm_k<<<ROWS,256>>>(x1,t0,n2g,n2b,out,nullptr);
}